// round 16
// baseline (speedup 1.0000x reference)
#include <cuda_runtime.h>
#include <cuda_fp16.h>
#include <math.h>
#include <stdint.h>

#define B_   2
#define S_   2048
#define D_   2048
#define H_   16
#define KVH_ 8
#define HD_  128
#define M_   (B_ * S_)          // 4096
#define NQ_  (H_ * HD_)         // 2048
#define NKV_ (KVH_ * HD_)       // 1024
#define EPS_ 1e-6f
#define SC_    0.08838834764831845f    // 1/sqrt(128)
#define LOG2E_ 1.4426950408889634f
#define GPERS  608                      // persistent CTAs (4 x 152 SMs)

// ---------------- scratch (device globals, allocation-free) ----------------
__device__ __align__(256) __half g_x16[M_ * D_];
__device__ __align__(256) __half g_a16[M_ * NQ_];
__device__ __align__(256) __half g_wq16[NQ_ * D_];
__device__ __align__(256) __half g_wk16[NKV_ * D_];
__device__ __align__(256) __half g_wv16[NKV_ * D_];
__device__ __align__(256) __half g_wo16[D_ * NQ_];
__device__ __align__(256) __half g_Q16[M_ * NQ_];
__device__ __align__(256) __half g_K16[M_ * NKV_];
__device__ __align__(256) __half g_V16[M_ * NKV_];
__device__ int g_tk[2];                 // work-steal tickets: [0]=qkv, [1]=o

// ---------------- PTX helpers (baseline PTX only) ----------------
__device__ __forceinline__ uint32_t smem_u32(const void* p) {
    uint32_t a;
    asm("{ .reg .u64 t; cvta.to.shared.u64 t, %1; cvt.u32.u64 %0, t; }" : "=r"(a) : "l"(p));
    return a;
}
__device__ __forceinline__ void cp16(uint32_t s, const void* g) {
    asm volatile("cp.async.cg.shared.global [%0], [%1], 16;" :: "r"(s), "l"(g));
}
#define CP_COMMIT() asm volatile("cp.async.commit_group;" ::: "memory")
#define CP_WAIT(n)  asm volatile("cp.async.wait_group %0;" :: "n"(n) : "memory")

__device__ __forceinline__ void ldm4(uint32_t* r, uint32_t addr) {
    asm volatile("ldmatrix.sync.aligned.m8n8.x4.shared.b16 {%0,%1,%2,%3}, [%4];"
                 : "=r"(r[0]), "=r"(r[1]), "=r"(r[2]), "=r"(r[3]) : "r"(addr));
}
__device__ __forceinline__ void ldm4t(uint32_t* r, uint32_t addr) {
    asm volatile("ldmatrix.sync.aligned.m8n8.x4.trans.shared.b16 {%0,%1,%2,%3}, [%4];"
                 : "=r"(r[0]), "=r"(r[1]), "=r"(r[2]), "=r"(r[3]) : "r"(addr));
}
__device__ __forceinline__ void mma16816(float* c, const uint32_t* a, const uint32_t* b) {
    asm volatile("mma.sync.aligned.m16n8k16.row.col.f32.f16.f16.f32 "
                 "{%0,%1,%2,%3}, {%4,%5,%6,%7}, {%8,%9}, {%0,%1,%2,%3};"
                 : "+f"(c[0]), "+f"(c[1]), "+f"(c[2]), "+f"(c[3])
                 : "r"(a[0]), "r"(a[1]), "r"(a[2]), "r"(a[3]), "r"(b[0]), "r"(b[1]));
}

__device__ __forceinline__ uint32_t sw128(uint32_t off) { return off ^ ((off >> 3) & 0x70); }
__device__ __forceinline__ uint32_t sw256(uint32_t off) { return off ^ ((off >> 4) & 0x70); }

__device__ __forceinline__ uint32_t packh2(float a, float b) {
    __half2 h = __floats2half2_rn(a, b);
    return *(uint32_t*)&h;
}
__device__ __forceinline__ float ex2(float x) {
    float y;
    asm("ex2.approx.f32 %0, %1;" : "=f"(y) : "f"(x));
    return y;
}

// ---------------- merged conversion kernel (+ ticket reset) ----------------
#define UX (M_ * D_ / 4)
#define UQ (NQ_ * D_ / 4)
#define UK (NKV_ * D_ / 4)
__global__ void cvt_all(const float* __restrict__ x,
                        const int* __restrict__ wq, const int* __restrict__ wk,
                        const int* __restrict__ wv, const int* __restrict__ wo) {
    int i = blockIdx.x * blockDim.x + threadIdx.x;
    if (i == 0) { g_tk[0] = GPERS; g_tk[1] = GPERS; }
    if (i < UX) {
        float4 v = ((const float4*)x)[i];
        uint2 p;
        p.x = packh2(v.x, v.y);
        p.y = packh2(v.z, v.w);
        ((uint2*)g_x16)[i] = p;
        return;
    }
    i -= UX;
    const int* src;
    __half* dst;
    int k;
    if (i < UQ)                    { src = wq; dst = g_wq16; k = i; }
    else if (i < UQ + UK)          { src = wk; dst = g_wk16; k = i - UQ; }
    else if (i < UQ + 2 * UK)      { src = wv; dst = g_wv16; k = i - UQ - UK; }
    else                           { src = wo; dst = g_wo16; k = i - UQ - 2 * UK; }
    int4 v = ((const int4*)src)[k];
    uint2 p;
    p.x = packh2((float)v.x, (float)v.y);
    p.y = packh2((float)v.z, (float)v.w);
    ((uint2*)dst)[k] = p;
}

// ---------------- GEMM mainloop: CTA 64x128, 4 warps 32x64, 2-stage -------
#define GTHREADS  128
#define GBM       64
#define GBK       64
#define GCHUNK    (D_ / GBK)          // 32
#define GA_B      (GBM * 128)         // 8KB
#define GW_B      (128 * 128)         // 16KB
#define GSTAGE_B  (GA_B + GW_B)       // 24KB
#define GSTG      2
#define GSMEM_DYN (GSTG * GSTAGE_B + 1024)   // ~49KB -> 4 CTAs/SM
#define EPAD      132

__device__ __forceinline__ void g_load_chunk(
    uint32_t tbase, int buf, int kc,
    const __half* __restrict__ A, const __half* __restrict__ W,
    int bm, int bn, int tid) {
    uint32_t st = tbase + buf * GSTAGE_B;
    const __half* Ap = A + (size_t)bm * D_ + kc * GBK;
    const __half* Wp = W + (size_t)bn * D_ + kc * GBK;
    #pragma unroll
    for (int t = 0; t < 4; t++) {               // A: 64 rows
        int idx = tid + t * GTHREADS;
        int row = idx >> 3;
        int seg = idx & 7;
        cp16(st + sw128((uint32_t)(row * 128 + seg * 16)),
             Ap + (size_t)row * D_ + seg * 8);
    }
    #pragma unroll
    for (int t = 0; t < 8; t++) {               // W: 128 rows
        int idx = tid + t * GTHREADS;
        int row = idx >> 3;
        int seg = idx & 7;
        cp16(st + GA_B + sw128((uint32_t)(row * 128 + seg * 16)),
             Wp + (size_t)row * D_ + seg * 8);
    }
    CP_COMMIT();
}

__device__ __forceinline__ void mma_mainloop(
    const __half* __restrict__ A, const __half* __restrict__ W,
    uint32_t tbase, int bm, int bn, int tid, float acc[2][8][4]) {
    const int wid = tid >> 5;
    const int L = tid & 31;
    const int wm = (wid & 1) * 32;
    const int wn = (wid >> 1) * 64;

    g_load_chunk(tbase, 0, 0, A, W, bm, bn, tid);
    g_load_chunk(tbase, 1, 1, A, W, bm, bn, tid);

    const int a_row = (L & 7) + ((L >> 3) & 1) * 8;
    const int a_kb  = (L >> 4) * 16;
    const int b_row = (L & 7) + ((L >> 4) << 3);
    const int b_kb  = ((L >> 3) & 1) * 16;

    for (int kc = 0; kc < GCHUNK; kc++) {
        const int buf = kc & 1;
        CP_WAIT(1);
        __syncthreads();

        uint32_t st = tbase + buf * GSTAGE_B;
        #pragma unroll
        for (int ks = 0; ks < 4; ks++) {
            uint32_t ah[2][4], bb[4][4];
            #pragma unroll
            for (int mi = 0; mi < 2; mi++) {
                uint32_t off = sw128((uint32_t)((wm + mi * 16 + a_row) * 128 + ks * 32 + a_kb));
                ldm4(ah[mi], st + off);
            }
            #pragma unroll
            for (int nj = 0; nj < 4; nj++) {
                uint32_t off = sw128((uint32_t)((wn + nj * 16 + b_row) * 128 + ks * 32 + b_kb));
                ldm4(bb[nj], st + GA_B + off);
            }
            #pragma unroll
            for (int mi = 0; mi < 2; mi++)
                #pragma unroll
                for (int j = 0; j < 8; j++)
                    mma16816(acc[mi][j], ah[mi], &bb[j >> 1][(j & 1) * 2]);
        }
        __syncthreads();
        if (kc + 2 < GCHUNK)
            g_load_chunk(tbase, buf, kc + 2, A, W, bm, bn, tid);
        else
            CP_COMMIT();
    }
}

// ---------------- fused QKV projection kernel (persistent) ----------------
#define NT_QKV (32 * (M_ / GBM))     // 2048 tiles

__global__ __launch_bounds__(GTHREADS, 4)
void gemm_qkv(const __half* __restrict__ A,
              const __half* __restrict__ Wq, const __half* __restrict__ Wk,
              const __half* __restrict__ Wv,
              const float* __restrict__ sq, const float* __restrict__ sk,
              const float* __restrict__ sv,
              const float* __restrict__ qnw, const float* __restrict__ knw,
              const float* __restrict__ cosc, const float* __restrict__ sinc,
              __half* __restrict__ Q, __half* __restrict__ K, __half* __restrict__ V) {
    extern __shared__ char dyns[];
    __shared__ int s_next;
    uint32_t tbase = (smem_u32(dyns) + 1023) & ~1023u;

    const int tid = threadIdx.x;
    const int wid = tid >> 5;
    const int L = tid & 31;
    const int g = L >> 2;
    const int q = L & 3;

    for (int t = blockIdx.x; t < NT_QKV; ) {
        const int bx = t & 31;
        const int bm = (t >> 5) * GBM;

        const __half* W;
        const float* scale;
        const float* nw;
        __half* Dst;
        int mode, h, nheads;
        if (bx < 16)      { W = Wq; scale = sq; nw = qnw; Dst = Q; mode = 0; h = bx;      nheads = H_;  }
        else if (bx < 24) { W = Wk; scale = sk; nw = knw; Dst = K; mode = 1; h = bx - 16; nheads = KVH_; }
        else              { W = Wv; scale = sv; nw = knw; Dst = V; mode = 2; h = bx - 24; nheads = KVH_; }
        const int bn = h * 128;

        float acc[2][8][4] = {};
        mma_mainloop(A, W, tbase, bm, bn, tid, acc);

        // epilogue: exchange acc through smem
        float* sm = (float*)dyns;
        __syncthreads();
        {
            const int wm = (wid & 1) * 32;
            const int wn = (wid >> 1) * 64;
            #pragma unroll
            for (int mi = 0; mi < 2; mi++) {
                int row = wm + mi * 16 + g;
                #pragma unroll
                for (int j = 0; j < 8; j++) {
                    int col = wn + j * 8 + 2 * q;
                    *(float2*)&sm[row * EPAD + col] = make_float2(acc[mi][j][0], acc[mi][j][1]);
                    *(float2*)&sm[(row + 8) * EPAD + col] = make_float2(acc[mi][j][2], acc[mi][j][3]);
                }
            }
            __syncthreads();
        }

        float eacc[16][4];
        const int r0l = wid * 16 + g;
        #pragma unroll
        for (int j = 0; j < 16; j++) {
            int c = j * 8 + 2 * q;
            float2 v0 = *(float2*)&sm[r0l * EPAD + c];
            float2 v1 = *(float2*)&sm[(r0l + 8) * EPAD + c];
            eacc[j][0] = v0.x; eacc[j][1] = v0.y;
            eacc[j][2] = v1.x; eacc[j][3] = v1.y;
        }

        const int r0 = bm + r0l;

        float ss0 = 0.0f, ss1 = 0.0f;
        #pragma unroll
        for (int j = 0; j < 16; j++) {
            int c = j * 8 + 2 * q;
            float s0 = __ldg(&scale[bn + c]);
            float s1 = __ldg(&scale[bn + c + 1]);
            eacc[j][0] *= s0; eacc[j][1] *= s1;
            eacc[j][2] *= s0; eacc[j][3] *= s1;
            ss0 += eacc[j][0] * eacc[j][0] + eacc[j][1] * eacc[j][1];
            ss1 += eacc[j][2] * eacc[j][2] + eacc[j][3] * eacc[j][3];
        }

        const int b = r0 >> 11;
        const int s0 = r0 & 2047;
        const int s1 = s0 + 8;
        size_t base0 = ((size_t)(b * nheads + h) * S_ + s0) * HD_;
        size_t base1 = ((size_t)(b * nheads + h) * S_ + s1) * HD_;

        if (mode == 2) {                    // V: plain fp16 convert
            #pragma unroll
            for (int j = 0; j < 16; j++) {
                int c = j * 8 + 2 * q;
                *(uint32_t*)&Dst[base0 + c] = packh2(eacc[j][0], eacc[j][1]);
                *(uint32_t*)&Dst[base1 + c] = packh2(eacc[j][2], eacc[j][3]);
            }
        } else {
            // Q/K: RMSNorm + RoPE (Q pre-scaled by log2e/sqrt(HD))
            ss0 += __shfl_xor_sync(0xffffffffu, ss0, 1);
            ss0 += __shfl_xor_sync(0xffffffffu, ss0, 2);
            ss1 += __shfl_xor_sync(0xffffffffu, ss1, 1);
            ss1 += __shfl_xor_sync(0xffffffffu, ss1, 2);
            float rms0 = rsqrtf(ss0 * (1.0f / HD_) + EPS_);
            float rms1 = rsqrtf(ss1 * (1.0f / HD_) + EPS_);
            if (mode == 0) { rms0 *= SC_ * LOG2E_; rms1 *= SC_ * LOG2E_; }

            #pragma unroll
            for (int j = 0; j < 8; j++) {
                int c = j * 8 + 2 * q;
                int cp = c + 64;
                float w0a = __ldg(&nw[c]),  float_w0b;
                float w0b = __ldg(&nw[c + 1]);
                (void)sizeof(float_w0b);
                float wpa = __ldg(&nw[cp]), wpb = __ldg(&nw[cp + 1]);
                float2 c0 = *(const float2*)&cosc[(size_t)s0 * HD_ + c];
                float2 n0 = *(const float2*)&sinc[(size_t)s0 * HD_ + c];
                float2 c1 = *(const float2*)&cosc[(size_t)s1 * HD_ + c];
                float2 n1 = *(const float2*)&sinc[(size_t)s1 * HD_ + c];

                float xa = eacc[j][0] * rms0 * w0a,     xb = eacc[j][1] * rms0 * w0b;
                float ya = eacc[j + 8][0] * rms0 * wpa, yb = eacc[j + 8][1] * rms0 * wpb;
                *(uint32_t*)&Dst[base0 + c]  = packh2(xa * c0.x - ya * n0.x, xb * c0.y - yb * n0.y);
                *(uint32_t*)&Dst[base0 + cp] = packh2(ya * c0.x + xa * n0.x, yb * c0.y + xb * n0.y);

                xa = eacc[j][2] * rms1 * w0a;     xb = eacc[j][3] * rms1 * w0b;
                ya = eacc[j + 8][2] * rms1 * wpa; yb = eacc[j + 8][3] * rms1 * wpb;
                *(uint32_t*)&Dst[base1 + c]  = packh2(xa * c1.x - ya * n1.x, xb * c1.y - yb * n1.y);
                *(uint32_t*)&Dst[base1 + cp] = packh2(ya * c1.x + xa * n1.x, yb * c1.y + xb * n1.y);
            }
        }

        // work-steal next tile
        __syncthreads();
        if (tid == 0) s_next = atomicAdd(&g_tk[0], 1);
        __syncthreads();
        t = s_next;
    }
}

// ---------------- O projection kernel (persistent, direct fp32 store) -----
#define NT_O (16 * (M_ / GBM))        // 1024 tiles

__global__ __launch_bounds__(GTHREADS, 4)
void gemm_o(const __half* __restrict__ A, const __half* __restrict__ W,
            const float* __restrict__ scale, float* __restrict__ C, int N) {
    extern __shared__ char dyns[];
    __shared__ int s_next;
    uint32_t tbase = (smem_u32(dyns) + 1023) & ~1023u;

    const int tid = threadIdx.x;
    const int wid = tid >> 5;
    const int L = tid & 31;
    const int wm = (wid & 1) * 32;
    const int wn = (wid >> 1) * 64;
    const int g = L >> 2;
    const int q = L & 3;

    for (int t = blockIdx.x; t < NT_O; ) {
        const int bn = (t & 15) * 128;
        const int bm = (t >> 4) * GBM;

        float acc[2][8][4] = {};
        mma_mainloop(A, W, tbase, bm, bn, tid, acc);

        #pragma unroll
        for (int mi = 0; mi < 2; mi++) {
            #pragma unroll
            for (int j = 0; j < 8; j++) {
                int col = bn + wn + j * 8 + q * 2;
                float s0 = __ldg(&scale[col]);
                float s1 = __ldg(&scale[col + 1]);
                int r0 = bm + wm + mi * 16 + g;
                *(float2*)&C[(size_t)r0 * N + col] =
                    make_float2(acc[mi][j][0] * s0, acc[mi][j][1] * s1);
                *(float2*)&C[(size_t)(r0 + 8) * N + col] =
                    make_float2(acc[mi][j][2] * s0, acc[mi][j][3] * s1);
            }
        }

        __syncthreads();
        if (tid == 0) s_next = atomicAdd(&g_tk[1], 1);
        __syncthreads();
        t = s_next;
    }
}

// ---------------- fp16 tensor-core flash attention (causal, GQA) -----------
#define BQA 64
#define BKVA 64
#define ATHREADS   128
#define AQ_BYTES   16384
#define AKV_STAGE  32768
#define AKV_STG    3
#define ASMEM (AQ_BYTES + AKV_STG * AKV_STAGE)   // 112KB

__device__ __forceinline__ void a_load_kv(uint32_t kvbase, int buf, int kt, int nkv,
                                          size_t kvoff, int tid) {
    if (kt < nkv) {
        int k0 = kt * BKVA;
        uint32_t st = kvbase + buf * AKV_STAGE;
        #pragma unroll
        for (int t = 0; t < 8; t++) {
            int idx = tid + t * ATHREADS;
            int row = idx >> 4;
            int ch = idx & 15;
            uint32_t off = sw256((uint32_t)(row * 256 + ch * 16));
            size_t gi = kvoff + (size_t)(k0 + row) * HD_ + ch * 8;
            cp16(st + off,         g_K16 + gi);
            cp16(st + 16384 + off, g_V16 + gi);
        }
    }
    CP_COMMIT();
}

__global__ __launch_bounds__(ATHREADS, 2)
void attn_mma() {
    extern __shared__ char smraw[];
    uint32_t sb = smem_u32(smraw);
    const int tid = threadIdx.x;
    const int wid = tid >> 5;
    const int L = tid & 31;
    const int g = L >> 2;
    const int qd = L & 3;

    const int qt = (int)gridDim.x - 1 - (int)blockIdx.x;
    const int bh = blockIdx.y;
    const int b = bh >> 4;
    const int h = bh & 15;
    const int kvh = h >> 1;
    const int q0 = qt * BQA;
    const int nkv = qt + 1;
    const int wm = wid * 16;

    const uint32_t Q_s = sb;
    const uint32_t kvbase = sb + AQ_BYTES;

    const __half* Qg = g_Q16 + ((size_t)bh * S_ + q0) * HD_;
    const size_t kvoff = (size_t)(b * KVH_ + kvh) * S_ * HD_;

    #pragma unroll
    for (int t = 0; t < 8; t++) {
        int idx = tid + t * ATHREADS;
        int row = idx >> 4;
        int ch = idx & 15;
        uint32_t off = sw256((uint32_t)(row * 256 + ch * 16));
        cp16(Q_s + off, Qg + (size_t)row * HD_ + ch * 8);
    }
    a_load_kv(kvbase, 0, 0, nkv, kvoff, tid);
    a_load_kv(kvbase, 1, 1, nkv, kvoff, tid);
    a_load_kv(kvbase, 2, 2, nkv, kvoff, tid);

    CP_WAIT(2);
    __syncthreads();
    uint32_t qf[8][4];
    {
        const uint32_t a_part = (uint32_t)((L & 15) * 256 + ((L >> 4) << 4));
        #pragma unroll
        for (int k16 = 0; k16 < 8; k16++)
            ldm4(qf[k16], Q_s + sw256((uint32_t)(wm * 256 + k16 * 32) + a_part));
    }

    float m0 = -1e30f, m1 = -1e30f, l0 = 0.0f, l1 = 0.0f;
    float oa[16][4] = {};

    int buf = 0;
    for (int kt = 0; kt < nkv; kt++) {
        CP_WAIT(2);
        __syncthreads();
        const int k0 = kt * BKVA;
        {
            uint32_t st = kvbase + buf * AKV_STAGE;
            uint32_t Kh = st, Vh = st + 16384;

            float sa[8][4] = {};
            const uint32_t b_row  = (uint32_t)((L & 7) + ((L >> 4) << 3));
            const uint32_t b_kb   = (uint32_t)(((L >> 3) & 1) * 16);
            #pragma unroll
            for (int k16 = 0; k16 < 8; k16++) {
                #pragma unroll
                for (int n16 = 0; n16 < 4; n16++) {
                    uint32_t boff = sw256((uint32_t)((n16 * 16 + b_row) * 256 + k16 * 32 + b_kb));
                    uint32_t kh4[4];
                    ldm4(kh4, Kh + boff);
                    mma16816(sa[n16 * 2],     qf[k16], &kh4[0]);
                    mma16816(sa[n16 * 2 + 1], qf[k16], &kh4[2]);
                }
            }

            const int r0 = q0 + wm + g;
            const int r1 = r0 + 8;
            if (k0 + 63 > q0 + wm) {
                #pragma unroll
                for (int t = 0; t < 8; t++) {
                    #pragma unroll
                    for (int c = 0; c < 4; c++) {
                        int col = k0 + t * 8 + 2 * qd + (c & 1);
                        int row = (c < 2) ? r0 : r1;
                        if (col > row) sa[t][c] = -1e30f;
                    }
                }
            }

            float mx0 = -1e30f, mx1 = -1e30f;
            #pragma unroll
            for (int t = 0; t < 8; t++) {
                mx0 = fmaxf(mx0, fmaxf(sa[t][0], sa[t][1]));
                mx1 = fmaxf(mx1, fmaxf(sa[t][2], sa[t][3]));
            }
            mx0 = fmaxf(mx0, __shfl_xor_sync(0xffffffffu, mx0, 1));
            mx0 = fmaxf(mx0, __shfl_xor_sync(0xffffffffu, mx0, 2));
            mx1 = fmaxf(mx1, __shfl_xor_sync(0xffffffffu, mx1, 1));
            mx1 = fmaxf(mx1, __shfl_xor_sync(0xffffffffu, mx1, 2));
            float nm0 = fmaxf(m0, mx0), nm1 = fmaxf(m1, mx1);

            // ballot-gated rescale: skip the 64-FMUL O-rescale when no row's
            // running max changed (true for most tiles after the first few)
            bool need = (nm0 > m0) || (nm1 > m1);
            uint32_t bal = __ballot_sync(0xffffffffu, need);
            float al0 = 1.0f, al1 = 1.0f;
            if (bal) {
                al0 = ex2(m0 - nm0);
                al1 = ex2(m1 - nm1);
                m0 = nm0; m1 = nm1;
            }

            float rs0 = 0.0f, rs1 = 0.0f;
            #pragma unroll
            for (int t = 0; t < 8; t++) {
                float p0 = ex2(sa[t][0] - m0);
                float p1 = ex2(sa[t][1] - m0);
                float p2 = ex2(sa[t][2] - m1);
                float p3 = ex2(sa[t][3] - m1);
                sa[t][0] = p0; sa[t][1] = p1; sa[t][2] = p2; sa[t][3] = p3;
                rs0 += p0 + p1; rs1 += p2 + p3;
            }
            rs0 += __shfl_xor_sync(0xffffffffu, rs0, 1);
            rs0 += __shfl_xor_sync(0xffffffffu, rs0, 2);
            rs1 += __shfl_xor_sync(0xffffffffu, rs1, 1);
            rs1 += __shfl_xor_sync(0xffffffffu, rs1, 2);

            if (bal) {
                l0 = l0 * al0 + rs0;
                l1 = l1 * al1 + rs1;
                #pragma unroll
                for (int nt = 0; nt < 16; nt++) {
                    oa[nt][0] *= al0; oa[nt][1] *= al0;
                    oa[nt][2] *= al1; oa[nt][3] *= al1;
                }
            } else {
                l0 += rs0;
                l1 += rs1;
            }

            const uint32_t v_row = (uint32_t)((L & 7) + ((L >> 3) & 1) * 8);
            const uint32_t v_cb  = (uint32_t)((L >> 4) << 4);
            #pragma unroll
            for (int kk = 0; kk < 4; kk++) {
                const int t0 = 2 * kk, t1 = t0 + 1;
                uint32_t ph[4];
                ph[0] = packh2(sa[t0][0], sa[t0][1]);
                ph[1] = packh2(sa[t0][2], sa[t0][3]);
                ph[2] = packh2(sa[t1][0], sa[t1][1]);
                ph[3] = packh2(sa[t1][2], sa[t1][3]);
                #pragma unroll
                for (int n16 = 0; n16 < 8; n16++) {
                    uint32_t voff = sw256((uint32_t)((kk * 16 + v_row) * 256 + n16 * 32) + v_cb);
                    uint32_t vh4[4];
                    ldm4t(vh4, Vh + voff);
                    mma16816(oa[n16 * 2],     ph, &vh4[0]);
                    mma16816(oa[n16 * 2 + 1], ph, &vh4[2]);
                }
            }
        }
        __syncthreads();
        a_load_kv(kvbase, buf, kt + AKV_STG, nkv, kvoff, tid);
        buf++; if (buf >= AKV_STG) buf = 0;
    }

    float inv0 = 1.0f / l0, inv1 = 1.0f / l1;
    const int r0 = q0 + wm + g;
    const int r1 = r0 + 8;
    size_t base0 = ((size_t)(b * S_) + r0) * NQ_ + h * HD_;
    size_t base1 = ((size_t)(b * S_) + r1) * NQ_ + h * HD_;
    #pragma unroll
    for (int nt = 0; nt < 16; nt++) {
        int c = nt * 8 + 2 * qd;
        *(uint32_t*)&g_a16[base0 + c] = packh2(oa[nt][0] * inv0, oa[nt][1] * inv0);
        *(uint32_t*)&g_a16[base1 + c] = packh2(oa[nt][2] * inv1, oa[nt][3] * inv1);
    }
}

// ---------------- launch ----------------
extern "C" void kernel_launch(void* const* d_in, const int* in_sizes, int n_in,
                              void* d_out, int out_size) {
    const float* x    = (const float*)d_in[0];
    const int*   wq   = (const int*)  d_in[1];
    const float* wqs  = (const float*)d_in[2];
    const int*   wk   = (const int*)  d_in[3];
    const float* wks  = (const float*)d_in[4];
    const int*   wv   = (const int*)  d_in[5];
    const float* wvs  = (const float*)d_in[6];
    const int*   wo   = (const int*)  d_in[7];
    const float* wos  = (const float*)d_in[8];
    const float* qnw  = (const float*)d_in[9];
    const float* knw  = (const float*)d_in[10];
    const float* cosc = (const float*)d_in[11];
    const float* sinc = (const float*)d_in[12];
    float* out = (float*)d_out;

    __half *x16, *a16, *wq16, *wk16, *wv16, *wo16, *Q16, *K16, *V16;
    cudaGetSymbolAddress((void**)&x16,  g_x16);
    cudaGetSymbolAddress((void**)&a16,  g_a16);
    cudaGetSymbolAddress((void**)&wq16, g_wq16);
    cudaGetSymbolAddress((void**)&wk16, g_wk16);
    cudaGetSymbolAddress((void**)&wv16, g_wv16);
    cudaGetSymbolAddress((void**)&wo16, g_wo16);
    cudaGetSymbolAddress((void**)&Q16,  g_Q16);
    cudaGetSymbolAddress((void**)&K16,  g_K16);
    cudaGetSymbolAddress((void**)&V16,  g_V16);

    cvt_all<<<(UX + 2 * UQ + 2 * UK) / 256, 256>>>(x, wq, wk, wv, wo);

    cudaFuncSetAttribute(gemm_qkv, cudaFuncAttributeMaxDynamicSharedMemorySize, GSMEM_DYN);
    cudaFuncSetAttribute(gemm_o,   cudaFuncAttributeMaxDynamicSharedMemorySize, GSMEM_DYN);

    gemm_qkv<<<GPERS, GTHREADS, GSMEM_DYN>>>(
        x16, wq16, wk16, wv16, wqs, wks, wvs, qnw, knw, cosc, sinc, Q16, K16, V16);

    cudaFuncSetAttribute(attn_mma, cudaFuncAttributeMaxDynamicSharedMemorySize, ASMEM);
    attn_mma<<<dim3(S_ / BQA, B_ * H_), ATHREADS, ASMEM>>>();

    gemm_o<<<GPERS, GTHREADS, GSMEM_DYN>>>(a16, wo16, wos, out, D_);
}

// round 17
// speedup vs baseline: 1.0121x; 1.0121x over previous
#include <cuda_runtime.h>
#include <cuda_fp16.h>
#include <math.h>
#include <stdint.h>

#define B_   2
#define S_   2048
#define D_   2048
#define H_   16
#define KVH_ 8
#define HD_  128
#define M_   (B_ * S_)          // 4096
#define NQ_  (H_ * HD_)         // 2048
#define NKV_ (KVH_ * HD_)       // 1024
#define EPS_ 1e-6f
#define SC_    0.08838834764831845f    // 1/sqrt(128)
#define LOG2E_ 1.4426950408889634f
#define GPERS  608                      // persistent CTAs (4 x 152 SMs)

// ---------------- scratch (device globals, allocation-free) ----------------
__device__ __align__(256) __half g_x16[M_ * D_];
__device__ __align__(256) __half g_a16[M_ * NQ_];
__device__ __align__(256) __half g_wq16[NQ_ * D_];
__device__ __align__(256) __half g_wk16[NKV_ * D_];
__device__ __align__(256) __half g_wv16[NKV_ * D_];
__device__ __align__(256) __half g_wo16[D_ * NQ_];
__device__ __align__(256) __half g_Q16[M_ * NQ_];
__device__ __align__(256) __half g_K16[M_ * NKV_];
__device__ __align__(256) __half g_V16[M_ * NKV_];
__device__ int g_tk[2];                 // work-steal tickets: [0]=qkv, [1]=o

// ---------------- PTX helpers (baseline PTX only) ----------------
__device__ __forceinline__ uint32_t smem_u32(const void* p) {
    uint32_t a;
    asm("{ .reg .u64 t; cvta.to.shared.u64 t, %1; cvt.u32.u64 %0, t; }" : "=r"(a) : "l"(p));
    return a;
}
__device__ __forceinline__ void cp16(uint32_t s, const void* g) {
    asm volatile("cp.async.cg.shared.global [%0], [%1], 16;" :: "r"(s), "l"(g));
}
#define CP_COMMIT() asm volatile("cp.async.commit_group;" ::: "memory")
#define CP_WAIT(n)  asm volatile("cp.async.wait_group %0;" :: "n"(n) : "memory")

__device__ __forceinline__ void ldm4(uint32_t* r, uint32_t addr) {
    asm volatile("ldmatrix.sync.aligned.m8n8.x4.shared.b16 {%0,%1,%2,%3}, [%4];"
                 : "=r"(r[0]), "=r"(r[1]), "=r"(r[2]), "=r"(r[3]) : "r"(addr));
}
__device__ __forceinline__ void ldm4t(uint32_t* r, uint32_t addr) {
    asm volatile("ldmatrix.sync.aligned.m8n8.x4.trans.shared.b16 {%0,%1,%2,%3}, [%4];"
                 : "=r"(r[0]), "=r"(r[1]), "=r"(r[2]), "=r"(r[3]) : "r"(addr));
}
__device__ __forceinline__ void mma16816(float* c, const uint32_t* a, const uint32_t* b) {
    asm volatile("mma.sync.aligned.m16n8k16.row.col.f32.f16.f16.f32 "
                 "{%0,%1,%2,%3}, {%4,%5,%6,%7}, {%8,%9}, {%0,%1,%2,%3};"
                 : "+f"(c[0]), "+f"(c[1]), "+f"(c[2]), "+f"(c[3])
                 : "r"(a[0]), "r"(a[1]), "r"(a[2]), "r"(a[3]), "r"(b[0]), "r"(b[1]));
}

__device__ __forceinline__ uint32_t sw128(uint32_t off) { return off ^ ((off >> 3) & 0x70); }
__device__ __forceinline__ uint32_t sw256(uint32_t off) { return off ^ ((off >> 4) & 0x70); }

__device__ __forceinline__ uint32_t packh2(float a, float b) {
    __half2 h = __floats2half2_rn(a, b);
    return *(uint32_t*)&h;
}
__device__ __forceinline__ float ex2(float x) {
    float y;
    asm("ex2.approx.f32 %0, %1;" : "=f"(y) : "f"(x));
    return y;
}

// ---------------- merged conversion kernel (+ ticket reset) ----------------
#define UX (M_ * D_ / 4)
#define UQ (NQ_ * D_ / 4)
#define UK (NKV_ * D_ / 4)
__global__ void cvt_all(const float* __restrict__ x,
                        const int* __restrict__ wq, const int* __restrict__ wk,
                        const int* __restrict__ wv, const int* __restrict__ wo) {
    int i = blockIdx.x * blockDim.x + threadIdx.x;
    if (i == 0) { g_tk[0] = GPERS; g_tk[1] = GPERS; }
    if (i < UX) {
        float4 v = ((const float4*)x)[i];
        uint2 p;
        p.x = packh2(v.x, v.y);
        p.y = packh2(v.z, v.w);
        ((uint2*)g_x16)[i] = p;
        return;
    }
    i -= UX;
    const int* src;
    __half* dst;
    int k;
    if (i < UQ)                    { src = wq; dst = g_wq16; k = i; }
    else if (i < UQ + UK)          { src = wk; dst = g_wk16; k = i - UQ; }
    else if (i < UQ + 2 * UK)      { src = wv; dst = g_wv16; k = i - UQ - UK; }
    else                           { src = wo; dst = g_wo16; k = i - UQ - 2 * UK; }
    int4 v = ((const int4*)src)[k];
    uint2 p;
    p.x = packh2((float)v.x, (float)v.y);
    p.y = packh2((float)v.z, (float)v.w);
    ((uint2*)dst)[k] = p;
}

// ---------------- GEMM mainloop: CTA 64x128, 4 warps 32x64, 2-stage -------
#define GTHREADS  128
#define GBM       64
#define GBK       64
#define GCHUNK    (D_ / GBK)          // 32
#define GA_B      (GBM * 128)         // 8KB
#define GW_B      (128 * 128)         // 16KB
#define GSTAGE_B  (GA_B + GW_B)       // 24KB
#define GSTG      2
#define GSMEM_DYN (GSTG * GSTAGE_B + 1024)   // ~49KB -> 4 CTAs/SM
#define EPAD      132

__device__ __forceinline__ void g_load_chunk(
    uint32_t tbase, int buf, int kc,
    const __half* __restrict__ A, const __half* __restrict__ W,
    int bm, int bn, int tid) {
    uint32_t st = tbase + buf * GSTAGE_B;
    const __half* Ap = A + (size_t)bm * D_ + kc * GBK;
    const __half* Wp = W + (size_t)bn * D_ + kc * GBK;
    #pragma unroll
    for (int t = 0; t < 4; t++) {               // A: 64 rows
        int idx = tid + t * GTHREADS;
        int row = idx >> 3;
        int seg = idx & 7;
        cp16(st + sw128((uint32_t)(row * 128 + seg * 16)),
             Ap + (size_t)row * D_ + seg * 8);
    }
    #pragma unroll
    for (int t = 0; t < 8; t++) {               // W: 128 rows
        int idx = tid + t * GTHREADS;
        int row = idx >> 3;
        int seg = idx & 7;
        cp16(st + GA_B + sw128((uint32_t)(row * 128 + seg * 16)),
             Wp + (size_t)row * D_ + seg * 8);
    }
    CP_COMMIT();
}

__device__ __forceinline__ void mma_mainloop(
    const __half* __restrict__ A, const __half* __restrict__ W,
    uint32_t tbase, int bm, int bn, int tid, float acc[2][8][4]) {
    const int wid = tid >> 5;
    const int L = tid & 31;
    const int wm = (wid & 1) * 32;
    const int wn = (wid >> 1) * 64;

    g_load_chunk(tbase, 0, 0, A, W, bm, bn, tid);
    g_load_chunk(tbase, 1, 1, A, W, bm, bn, tid);

    const int a_row = (L & 7) + ((L >> 3) & 1) * 8;
    const int a_kb  = (L >> 4) * 16;
    const int b_row = (L & 7) + ((L >> 4) << 3);
    const int b_kb  = ((L >> 3) & 1) * 16;

    for (int kc = 0; kc < GCHUNK; kc++) {
        const int buf = kc & 1;
        CP_WAIT(1);
        __syncthreads();

        uint32_t st = tbase + buf * GSTAGE_B;
        #pragma unroll
        for (int ks = 0; ks < 4; ks++) {
            uint32_t ah[2][4], bb[4][4];
            #pragma unroll
            for (int mi = 0; mi < 2; mi++) {
                uint32_t off = sw128((uint32_t)((wm + mi * 16 + a_row) * 128 + ks * 32 + a_kb));
                ldm4(ah[mi], st + off);
            }
            #pragma unroll
            for (int nj = 0; nj < 4; nj++) {
                uint32_t off = sw128((uint32_t)((wn + nj * 16 + b_row) * 128 + ks * 32 + b_kb));
                ldm4(bb[nj], st + GA_B + off);
            }
            #pragma unroll
            for (int mi = 0; mi < 2; mi++)
                #pragma unroll
                for (int j = 0; j < 8; j++)
                    mma16816(acc[mi][j], ah[mi], &bb[j >> 1][(j & 1) * 2]);
        }
        __syncthreads();
        if (kc + 2 < GCHUNK)
            g_load_chunk(tbase, buf, kc + 2, A, W, bm, bn, tid);
        else
            CP_COMMIT();
    }
}

// ---------------- fused QKV projection kernel (persistent) ----------------
#define NT_QKV (32 * (M_ / GBM))     // 2048 tiles

__global__ __launch_bounds__(GTHREADS, 4)
void gemm_qkv(const __half* __restrict__ A,
              const __half* __restrict__ Wq, const __half* __restrict__ Wk,
              const __half* __restrict__ Wv,
              const float* __restrict__ sq, const float* __restrict__ sk,
              const float* __restrict__ sv,
              const float* __restrict__ qnw, const float* __restrict__ knw,
              const float* __restrict__ cosc, const float* __restrict__ sinc,
              __half* __restrict__ Q, __half* __restrict__ K, __half* __restrict__ V) {
    extern __shared__ char dyns[];
    __shared__ int s_next;
    uint32_t tbase = (smem_u32(dyns) + 1023) & ~1023u;

    const int tid = threadIdx.x;
    const int wid = tid >> 5;
    const int L = tid & 31;
    const int g = L >> 2;
    const int q = L & 3;

    for (int t = blockIdx.x; t < NT_QKV; ) {
        const int bx = t & 31;
        const int bm = (t >> 5) * GBM;

        const __half* W;
        const float* scale;
        const float* nw;
        __half* Dst;
        int mode, h, nheads;
        if (bx < 16)      { W = Wq; scale = sq; nw = qnw; Dst = Q; mode = 0; h = bx;      nheads = H_;  }
        else if (bx < 24) { W = Wk; scale = sk; nw = knw; Dst = K; mode = 1; h = bx - 16; nheads = KVH_; }
        else              { W = Wv; scale = sv; nw = knw; Dst = V; mode = 2; h = bx - 24; nheads = KVH_; }
        const int bn = h * 128;

        float acc[2][8][4] = {};
        mma_mainloop(A, W, tbase, bm, bn, tid, acc);

        // epilogue: exchange acc through smem
        float* sm = (float*)dyns;
        __syncthreads();
        {
            const int wm = (wid & 1) * 32;
            const int wn = (wid >> 1) * 64;
            #pragma unroll
            for (int mi = 0; mi < 2; mi++) {
                int row = wm + mi * 16 + g;
                #pragma unroll
                for (int j = 0; j < 8; j++) {
                    int col = wn + j * 8 + 2 * q;
                    *(float2*)&sm[row * EPAD + col] = make_float2(acc[mi][j][0], acc[mi][j][1]);
                    *(float2*)&sm[(row + 8) * EPAD + col] = make_float2(acc[mi][j][2], acc[mi][j][3]);
                }
            }
            __syncthreads();
        }

        float eacc[16][4];
        const int r0l = wid * 16 + g;
        #pragma unroll
        for (int j = 0; j < 16; j++) {
            int c = j * 8 + 2 * q;
            float2 v0 = *(float2*)&sm[r0l * EPAD + c];
            float2 v1 = *(float2*)&sm[(r0l + 8) * EPAD + c];
            eacc[j][0] = v0.x; eacc[j][1] = v0.y;
            eacc[j][2] = v1.x; eacc[j][3] = v1.y;
        }

        const int r0 = bm + r0l;

        float ss0 = 0.0f, ss1 = 0.0f;
        #pragma unroll
        for (int j = 0; j < 16; j++) {
            int c = j * 8 + 2 * q;
            float s0 = __ldg(&scale[bn + c]);
            float s1 = __ldg(&scale[bn + c + 1]);
            eacc[j][0] *= s0; eacc[j][1] *= s1;
            eacc[j][2] *= s0; eacc[j][3] *= s1;
            ss0 += eacc[j][0] * eacc[j][0] + eacc[j][1] * eacc[j][1];
            ss1 += eacc[j][2] * eacc[j][2] + eacc[j][3] * eacc[j][3];
        }

        const int b = r0 >> 11;
        const int s0 = r0 & 2047;
        const int s1 = s0 + 8;
        size_t base0 = ((size_t)(b * nheads + h) * S_ + s0) * HD_;
        size_t base1 = ((size_t)(b * nheads + h) * S_ + s1) * HD_;

        if (mode == 2) {                    // V: plain fp16 convert
            #pragma unroll
            for (int j = 0; j < 16; j++) {
                int c = j * 8 + 2 * q;
                *(uint32_t*)&Dst[base0 + c] = packh2(eacc[j][0], eacc[j][1]);
                *(uint32_t*)&Dst[base1 + c] = packh2(eacc[j][2], eacc[j][3]);
            }
        } else {
            // Q/K: RMSNorm + RoPE (Q pre-scaled by log2e/sqrt(HD))
            ss0 += __shfl_xor_sync(0xffffffffu, ss0, 1);
            ss0 += __shfl_xor_sync(0xffffffffu, ss0, 2);
            ss1 += __shfl_xor_sync(0xffffffffu, ss1, 1);
            ss1 += __shfl_xor_sync(0xffffffffu, ss1, 2);
            float rms0 = rsqrtf(ss0 * (1.0f / HD_) + EPS_);
            float rms1 = rsqrtf(ss1 * (1.0f / HD_) + EPS_);
            if (mode == 0) { rms0 *= SC_ * LOG2E_; rms1 *= SC_ * LOG2E_; }

            #pragma unroll
            for (int j = 0; j < 8; j++) {
                int c = j * 8 + 2 * q;
                int cp = c + 64;
                float w0a = __ldg(&nw[c]),  w0b = __ldg(&nw[c + 1]);
                float wpa = __ldg(&nw[cp]), wpb = __ldg(&nw[cp + 1]);
                float2 c0 = *(const float2*)&cosc[(size_t)s0 * HD_ + c];
                float2 n0 = *(const float2*)&sinc[(size_t)s0 * HD_ + c];
                float2 c1 = *(const float2*)&cosc[(size_t)s1 * HD_ + c];
                float2 n1 = *(const float2*)&sinc[(size_t)s1 * HD_ + c];

                float xa = eacc[j][0] * rms0 * w0a,     xb = eacc[j][1] * rms0 * w0b;
                float ya = eacc[j + 8][0] * rms0 * wpa, yb = eacc[j + 8][1] * rms0 * wpb;
                *(uint32_t*)&Dst[base0 + c]  = packh2(xa * c0.x - ya * n0.x, xb * c0.y - yb * n0.y);
                *(uint32_t*)&Dst[base0 + cp] = packh2(ya * c0.x + xa * n0.x, yb * c0.y + xb * n0.y);

                xa = eacc[j][2] * rms1 * w0a;     xb = eacc[j][3] * rms1 * w0b;
                ya = eacc[j + 8][2] * rms1 * wpa; yb = eacc[j + 8][3] * rms1 * wpb;
                *(uint32_t*)&Dst[base1 + c]  = packh2(xa * c1.x - ya * n1.x, xb * c1.y - yb * n1.y);
                *(uint32_t*)&Dst[base1 + cp] = packh2(ya * c1.x + xa * n1.x, yb * c1.y + xb * n1.y);
            }
        }

        // work-steal next tile
        __syncthreads();
        if (tid == 0) s_next = atomicAdd(&g_tk[0], 1);
        __syncthreads();
        t = s_next;
    }
}

// ---------------- O projection kernel (persistent, direct fp32 store) -----
#define NT_O (16 * (M_ / GBM))        // 1024 tiles

__global__ __launch_bounds__(GTHREADS, 4)
void gemm_o(const __half* __restrict__ A, const __half* __restrict__ W,
            const float* __restrict__ scale, float* __restrict__ C, int N) {
    extern __shared__ char dyns[];
    __shared__ int s_next;
    uint32_t tbase = (smem_u32(dyns) + 1023) & ~1023u;

    const int tid = threadIdx.x;
    const int wid = tid >> 5;
    const int L = tid & 31;
    const int wm = (wid & 1) * 32;
    const int wn = (wid >> 1) * 64;
    const int g = L >> 2;
    const int q = L & 3;

    for (int t = blockIdx.x; t < NT_O; ) {
        const int bn = (t & 15) * 128;
        const int bm = (t >> 4) * GBM;

        float acc[2][8][4] = {};
        mma_mainloop(A, W, tbase, bm, bn, tid, acc);

        #pragma unroll
        for (int mi = 0; mi < 2; mi++) {
            #pragma unroll
            for (int j = 0; j < 8; j++) {
                int col = bn + wn + j * 8 + q * 2;
                float s0 = __ldg(&scale[col]);
                float s1 = __ldg(&scale[col + 1]);
                int r0 = bm + wm + mi * 16 + g;
                *(float2*)&C[(size_t)r0 * N + col] =
                    make_float2(acc[mi][j][0] * s0, acc[mi][j][1] * s1);
                *(float2*)&C[(size_t)(r0 + 8) * N + col] =
                    make_float2(acc[mi][j][2] * s0, acc[mi][j][3] * s1);
            }
        }

        __syncthreads();
        if (tid == 0) s_next = atomicAdd(&g_tk[1], 1);
        __syncthreads();
        t = s_next;
    }
}

// ---------------- fp16 tensor-core flash attention (causal, GQA) -----------
// 64-row q tiles, 4 warps, 2 CTAs/SM, 3-stage KV pipeline with ONE sync/tile.
#define BQA 64
#define BKVA 64
#define ATHREADS   128
#define AQ_BYTES   16384
#define AKV_STAGE  32768
#define AKV_STG    3
#define ASMEM (AQ_BYTES + AKV_STG * AKV_STAGE)   // 112KB

__device__ __forceinline__ void a_load_kv(uint32_t kvbase, int buf, int kt, int nkv,
                                          size_t kvoff, int tid) {
    if (kt < nkv) {
        int k0 = kt * BKVA;
        uint32_t st = kvbase + buf * AKV_STAGE;
        #pragma unroll
        for (int t = 0; t < 8; t++) {
            int idx = tid + t * ATHREADS;
            int row = idx >> 4;
            int ch = idx & 15;
            uint32_t off = sw256((uint32_t)(row * 256 + ch * 16));
            size_t gi = kvoff + (size_t)(k0 + row) * HD_ + ch * 8;
            cp16(st + off,         g_K16 + gi);
            cp16(st + 16384 + off, g_V16 + gi);
        }
    }
    CP_COMMIT();
}

__global__ __launch_bounds__(ATHREADS, 2)
void attn_mma() {
    extern __shared__ char smraw[];
    uint32_t sb = smem_u32(smraw);
    const int tid = threadIdx.x;
    const int wid = tid >> 5;
    const int L = tid & 31;
    const int g = L >> 2;
    const int qd = L & 3;

    const int qt = (int)gridDim.x - 1 - (int)blockIdx.x;
    const int bh = blockIdx.y;
    const int b = bh >> 4;
    const int h = bh & 15;
    const int kvh = h >> 1;
    const int q0 = qt * BQA;
    const int nkv = qt + 1;
    const int wm = wid * 16;

    const uint32_t Q_s = sb;
    const uint32_t kvbase = sb + AQ_BYTES;

    const __half* Qg = g_Q16 + ((size_t)bh * S_ + q0) * HD_;
    const size_t kvoff = (size_t)(b * KVH_ + kvh) * S_ * HD_;

    // prologue: G0 = Q + kv0, G1 = kv1
    #pragma unroll
    for (int t = 0; t < 8; t++) {
        int idx = tid + t * ATHREADS;
        int row = idx >> 4;
        int ch = idx & 15;
        uint32_t off = sw256((uint32_t)(row * 256 + ch * 16));
        cp16(Q_s + off, Qg + (size_t)row * HD_ + ch * 8);
    }
    a_load_kv(kvbase, 0, 0, nkv, kvoff, tid);    // G0 (Q + kv0)
    a_load_kv(kvbase, 1, 1, nkv, kvoff, tid);    // G1 (kv1)

    // Q fragments (needs G0 done)
    CP_WAIT(1);
    __syncthreads();
    uint32_t qf[8][4];
    {
        const uint32_t a_part = (uint32_t)((L & 15) * 256 + ((L >> 4) << 4));
        #pragma unroll
        for (int k16 = 0; k16 < 8; k16++)
            ldm4(qf[k16], Q_s + sw256((uint32_t)(wm * 256 + k16 * 32) + a_part));
    }

    float m0 = -1e30f, m1 = -1e30f, l0 = 0.0f, l1 = 0.0f;
    float oa[16][4] = {};

    for (int kt = 0; kt < nkv; kt++) {
        // kv(kt) ready after wait(1); sync also closes prev compute so the
        // (kt+2)%3 buffer (held kv(kt-1)) is reusable -> ONE sync per tile.
        CP_WAIT(1);
        __syncthreads();
        a_load_kv(kvbase, (kt + 2) % AKV_STG, kt + 2, nkv, kvoff, tid);

        const int k0 = kt * BKVA;
        uint32_t st = kvbase + (kt % AKV_STG) * AKV_STAGE;
        uint32_t Kh = st, Vh = st + 16384;

        float sa[8][4] = {};
        const uint32_t b_row  = (uint32_t)((L & 7) + ((L >> 4) << 3));
        const uint32_t b_kb   = (uint32_t)(((L >> 3) & 1) * 16);
        #pragma unroll
        for (int k16 = 0; k16 < 8; k16++) {
            #pragma unroll
            for (int n16 = 0; n16 < 4; n16++) {
                uint32_t boff = sw256((uint32_t)((n16 * 16 + b_row) * 256 + k16 * 32 + b_kb));
                uint32_t kh4[4];
                ldm4(kh4, Kh + boff);
                mma16816(sa[n16 * 2],     qf[k16], &kh4[0]);
                mma16816(sa[n16 * 2 + 1], qf[k16], &kh4[2]);
            }
        }

        const int r0 = q0 + wm + g;
        const int r1 = r0 + 8;
        if (k0 + 63 > q0 + wm) {
            #pragma unroll
            for (int t = 0; t < 8; t++) {
                #pragma unroll
                for (int c = 0; c < 4; c++) {
                    int col = k0 + t * 8 + 2 * qd + (c & 1);
                    int row = (c < 2) ? r0 : r1;
                    if (col > row) sa[t][c] = -1e30f;
                }
            }
        }

        float mx0 = -1e30f, mx1 = -1e30f;
        #pragma unroll
        for (int t = 0; t < 8; t++) {
            mx0 = fmaxf(mx0, fmaxf(sa[t][0], sa[t][1]));
            mx1 = fmaxf(mx1, fmaxf(sa[t][2], sa[t][3]));
        }
        mx0 = fmaxf(mx0, __shfl_xor_sync(0xffffffffu, mx0, 1));
        mx0 = fmaxf(mx0, __shfl_xor_sync(0xffffffffu, mx0, 2));
        mx1 = fmaxf(mx1, __shfl_xor_sync(0xffffffffu, mx1, 1));
        mx1 = fmaxf(mx1, __shfl_xor_sync(0xffffffffu, mx1, 2));
        float nm0 = fmaxf(m0, mx0), nm1 = fmaxf(m1, mx1);
        float al0 = ex2(m0 - nm0), al1 = ex2(m1 - nm1);
        m0 = nm0; m1 = nm1;
        float rs0 = 0.0f, rs1 = 0.0f;
        #pragma unroll
        for (int t = 0; t < 8; t++) {
            float p0 = ex2(sa[t][0] - m0);
            float p1 = ex2(sa[t][1] - m0);
            float p2 = ex2(sa[t][2] - m1);
            float p3 = ex2(sa[t][3] - m1);
            sa[t][0] = p0; sa[t][1] = p1; sa[t][2] = p2; sa[t][3] = p3;
            rs0 += p0 + p1; rs1 += p2 + p3;
        }
        rs0 += __shfl_xor_sync(0xffffffffu, rs0, 1);
        rs0 += __shfl_xor_sync(0xffffffffu, rs0, 2);
        rs1 += __shfl_xor_sync(0xffffffffu, rs1, 1);
        rs1 += __shfl_xor_sync(0xffffffffu, rs1, 2);
        l0 = l0 * al0 + rs0;
        l1 = l1 * al1 + rs1;
        #pragma unroll
        for (int nt = 0; nt < 16; nt++) {
            oa[nt][0] *= al0; oa[nt][1] *= al0;
            oa[nt][2] *= al1; oa[nt][3] *= al1;
        }

        const uint32_t v_row = (uint32_t)((L & 7) + ((L >> 3) & 1) * 8);
        const uint32_t v_cb  = (uint32_t)((L >> 4) << 4);
        #pragma unroll
        for (int kk = 0; kk < 4; kk++) {
            const int t0 = 2 * kk, t1 = t0 + 1;
            uint32_t ph[4];
            ph[0] = packh2(sa[t0][0], sa[t0][1]);
            ph[1] = packh2(sa[t0][2], sa[t0][3]);
            ph[2] = packh2(sa[t1][0], sa[t1][1]);
            ph[3] = packh2(sa[t1][2], sa[t1][3]);
            #pragma unroll
            for (int n16 = 0; n16 < 8; n16++) {
                uint32_t voff = sw256((uint32_t)((kk * 16 + v_row) * 256 + n16 * 32) + v_cb);
                uint32_t vh4[4];
                ldm4t(vh4, Vh + voff);
                mma16816(oa[n16 * 2],     ph, &vh4[0]);
                mma16816(oa[n16 * 2 + 1], ph, &vh4[2]);
            }
        }
    }

    float inv0 = 1.0f / l0, inv1 = 1.0f / l1;
    const int r0 = q0 + wm + g;
    const int r1 = r0 + 8;
    size_t base0 = ((size_t)(b * S_) + r0) * NQ_ + h * HD_;
    size_t base1 = ((size_t)(b * S_) + r1) * NQ_ + h * HD_;
    #pragma unroll
    for (int nt = 0; nt < 16; nt++) {
        int c = nt * 8 + 2 * qd;
        *(uint32_t*)&g_a16[base0 + c] = packh2(oa[nt][0] * inv0, oa[nt][1] * inv0);
        *(uint32_t*)&g_a16[base1 + c] = packh2(oa[nt][2] * inv1, oa[nt][3] * inv1);
    }
}

// ---------------- launch ----------------
extern "C" void kernel_launch(void* const* d_in, const int* in_sizes, int n_in,
                              void* d_out, int out_size) {
    const float* x    = (const float*)d_in[0];
    const int*   wq   = (const int*)  d_in[1];
    const float* wqs  = (const float*)d_in[2];
    const int*   wk   = (const int*)  d_in[3];
    const float* wks  = (const float*)d_in[4];
    const int*   wv   = (const int*)  d_in[5];
    const float* wvs  = (const float*)d_in[6];
    const int*   wo   = (const int*)  d_in[7];
    const float* wos  = (const float*)d_in[8];
    const float* qnw  = (const float*)d_in[9];
    const float* knw  = (const float*)d_in[10];
    const float* cosc = (const float*)d_in[11];
    const float* sinc = (const float*)d_in[12];
    float* out = (float*)d_out;

    __half *x16, *a16, *wq16, *wk16, *wv16, *wo16, *Q16, *K16, *V16;
    cudaGetSymbolAddress((void**)&x16,  g_x16);
    cudaGetSymbolAddress((void**)&a16,  g_a16);
    cudaGetSymbolAddress((void**)&wq16, g_wq16);
    cudaGetSymbolAddress((void**)&wk16, g_wk16);
    cudaGetSymbolAddress((void**)&wv16, g_wv16);
    cudaGetSymbolAddress((void**)&wo16, g_wo16);
    cudaGetSymbolAddress((void**)&Q16,  g_Q16);
    cudaGetSymbolAddress((void**)&K16,  g_K16);
    cudaGetSymbolAddress((void**)&V16,  g_V16);

    cvt_all<<<(UX + 2 * UQ + 2 * UK) / 256, 256>>>(x, wq, wk, wv, wo);

    cudaFuncSetAttribute(gemm_qkv, cudaFuncAttributeMaxDynamicSharedMemorySize, GSMEM_DYN);
    cudaFuncSetAttribute(gemm_o,   cudaFuncAttributeMaxDynamicSharedMemorySize, GSMEM_DYN);

    gemm_qkv<<<GPERS, GTHREADS, GSMEM_DYN>>>(
        x16, wq16, wk16, wv16, wqs, wks, wvs, qnw, knw, cosc, sinc, Q16, K16, V16);

    cudaFuncSetAttribute(attn_mma, cudaFuncAttributeMaxDynamicSharedMemorySize, ASMEM);
    attn_mma<<<dim3(S_ / BQA, B_ * H_), ATHREADS, ASMEM>>>();

    gemm_o<<<GPERS, GTHREADS, GSMEM_DYN>>>(a16, wo16, wos, out, D_);
}